// round 8
// baseline (speedup 1.0000x reference)
#include <cuda_runtime.h>
#include <cuda_bf16.h>
#include <cstdint>

// ============================================================================
// DigitConvolutionalModel: conv folds into W1 -> pure 4-layer MLP
//   784 -> 200 -> 200 -> 200 -> 10, batch 65536, fp32 in/out.
// bf16x3 split arithmetic, mma.sync.m16n8k16. CTA = 64 rows, 256 threads.
// Warp grid 2M x 4N (j-split {7,7,6,6}) -> W-fragment redundancy 4x -> 2x.
// h stored plane-major as MMA A-fragments: hf[ks][mtile][reg][lane]
// (producer STS and consumer LDS both conflict-free, zero repack cost).
// 3-deep cp.async ring, one __syncthreads per k-chunk. 2 CTAs/SM.
// ============================================================================

#define CTA_THREADS 256

#define NK1 49
#define NKH 13
#define NJH 26
#define NJO 2

// fragment-linear weights: uint4 per (ks, j, lane) = {b0h, b1h, b0l, b1l}
__device__ uint4 g_Wb1[NK1 * NJH * 32];
__device__ uint4 g_Wb2[NKH * NJH * 32];
__device__ uint4 g_Wb3[NKH * NJH * 32];
__device__ uint4 g_Wb4[NKH * NJO * 32];

// ---------------------------------------------------------------------------
__device__ __forceinline__ void split_pack(float x, float y, uint32_t& h, uint32_t& l) {
    __nv_bfloat16 hx = __float2bfloat16_rn(x);
    __nv_bfloat16 hy = __float2bfloat16_rn(y);
    float rx = x - __bfloat162float(hx);
    float ry = y - __bfloat162float(hy);
    __nv_bfloat162 H; H.x = hx; H.y = hy;
    __nv_bfloat162 L; L.x = __float2bfloat16_rn(rx); L.y = __float2bfloat16_rn(ry);
    h = *reinterpret_cast<uint32_t*>(&H);
    l = *reinterpret_cast<uint32_t*>(&L);
}

__device__ __forceinline__ void mma_bf16(float* c, const uint32_t* a,
                                         uint32_t b0, uint32_t b1) {
    asm volatile(
        "mma.sync.aligned.m16n8k16.row.col.f32.bf16.bf16.f32 "
        "{%0,%1,%2,%3},{%4,%5,%6,%7},{%8,%9},{%0,%1,%2,%3};"
        : "+f"(c[0]), "+f"(c[1]), "+f"(c[2]), "+f"(c[3])
        : "r"(a[0]), "r"(a[1]), "r"(a[2]), "r"(a[3]), "r"(b0), "r"(b1));
}

__device__ __forceinline__ void cp16(void* dst_smem, const void* src) {
    uint32_t d = (uint32_t)__cvta_generic_to_shared(dst_smem);
    asm volatile("cp.async.cg.shared.global [%0], [%1], 16;" :: "r"(d), "l"(src));
}
#define CP_COMMIT asm volatile("cp.async.commit_group;" ::: "memory")
#define CP_WAIT1  asm volatile("cp.async.wait_group 1;" ::: "memory")

// ---------------------------------------------------------------------------
// prep kernel (unchanged layout)
// ---------------------------------------------------------------------------
__device__ __forceinline__ float w_l1(const float* cw, const float* W1, int k, int n) {
    if (n >= 200) return 0.f;
    int r = k / 28, c = k % 28;
    float s = 0.f;
    #pragma unroll
    for (int dy = 0; dy < 3; ++dy) {
        int i = r - dy;
        if (i < 0 || i > 25) continue;
        #pragma unroll
        for (int dx = 0; dx < 3; ++dx) {
            int j = c - dx;
            if (j < 0 || j > 25) continue;
            s += cw[dy * 3 + dx] * W1[(i * 26 + j) * 200 + n];
        }
    }
    return s;
}

__global__ void prep_kernel(const float* __restrict__ cw,
                            const float* __restrict__ W1,
                            const float* __restrict__ W2,
                            const float* __restrict__ W3,
                            const float* __restrict__ W4) {
    int s = blockIdx.x * CTA_THREADS + threadIdx.x;
    const int E1 = NK1 * NJH * 32;
    const int E2 = E1 + NKH * NJH * 32;
    const int E3 = E2 + NKH * NJH * 32;
    const int E4 = E3 + NKH * NJO * 32;
    if (s >= E4) return;

    uint4* dst; int loc, nj, which;
    if (s < E1)      { dst = g_Wb1; loc = s;      nj = NJH; which = 1; }
    else if (s < E2) { dst = g_Wb2; loc = s - E1; nj = NJH; which = 2; }
    else if (s < E3) { dst = g_Wb3; loc = s - E2; nj = NJH; which = 3; }
    else             { dst = g_Wb4; loc = s - E3; nj = NJO; which = 4; }

    int lane = loc & 31;
    int j    = (loc >> 5) % nj;
    int ks   = loc / (nj * 32);
    int g = lane >> 2, t = lane & 3;
    int n  = 8 * j + g;
    int k0 = 16 * ks + 2 * t;

    float w0, w1, w8, w9;
    if (which == 1) {
        w0 = w_l1(cw, W1, k0,     n);
        w1 = w_l1(cw, W1, k0 + 1, n);
        w8 = w_l1(cw, W1, k0 + 8, n);
        w9 = w_l1(cw, W1, k0 + 9, n);
    } else if (which == 4) {
        w0 = (k0     < 200 && n < 10) ? W4[(k0)     * 10 + n] : 0.f;
        w1 = (k0 + 1 < 200 && n < 10) ? W4[(k0 + 1) * 10 + n] : 0.f;
        w8 = (k0 + 8 < 200 && n < 10) ? W4[(k0 + 8) * 10 + n] : 0.f;
        w9 = (k0 + 9 < 200 && n < 10) ? W4[(k0 + 9) * 10 + n] : 0.f;
    } else {
        const float* W = (which == 2) ? W2 : W3;
        w0 = (k0     < 200 && n < 200) ? W[(k0)     * 200 + n] : 0.f;
        w1 = (k0 + 1 < 200 && n < 200) ? W[(k0 + 1) * 200 + n] : 0.f;
        w8 = (k0 + 8 < 200 && n < 200) ? W[(k0 + 8) * 200 + n] : 0.f;
        w9 = (k0 + 9 < 200 && n < 200) ? W[(k0 + 9) * 200 + n] : 0.f;
    }

    uint32_t b0h, b0l, b1h, b1l;
    split_pack(w0, w1, b0h, b0l);
    split_pack(w8, w9, b1h, b1l);
    dst[loc] = make_uint4(b0h, b1h, b0l, b1l);
}

// ---------------------------------------------------------------------------
// main fused kernel
// SMEM (floats):
//   [0,3840)        xs: 3 x [64][20] fp32 x-stage (stride 20)
//   [3840,13824)    ws: 3 x [832] uint4 weight stage
//   [13824,20480)   hfh: [13][4][4][32] u32  A-fragments hi (26624 B)
//   [20480,27136)   hfl: same, lo
//   [27136,27776)   sb: biases
// ---------------------------------------------------------------------------
#define SMEM_BYTES 111104

__global__ void __launch_bounds__(CTA_THREADS, 2)
mlp_kernel(const float* __restrict__ x,
           const float* __restrict__ b1, const float* __restrict__ b2,
           const float* __restrict__ b3, const float* __restrict__ b4,
           float* __restrict__ out) {
    extern __shared__ float smf[];
    float*    xs  = smf;                               // 3 x 1280 floats
    uint4*    ws  = (uint4*)(smf + 3840);              // 3 x 832 uint4
    uint32_t* hfh = (uint32_t*)(smf + 13824);          // 13*4*4*32 u32
    uint32_t* hfl = (uint32_t*)(smf + 20480);
    float*    sb  = smf + 27136;

    const int tid  = threadIdx.x;
    const int lane = tid & 31;
    const int warp = tid >> 5;
    const int g = lane >> 2, t = lane & 3;
    const int mh = warp >> 2;                  // M-half: rows mh*32..mh*32+31
    const int nq = warp & 3;                   // N-quarter
    const int js  = (nq < 2) ? nq * 7 : 14 + (nq - 2) * 6;   // j-tile start
    const int cnt = (nq < 2) ? 7 : 6;                        // j-tile count
    const int r0 = blockIdx.x * 64;

    if (tid < 208) {
        sb[tid]       = (tid < 200) ? b1[tid] : 0.f;
        sb[208 + tid] = (tid < 200) ? b2[tid] : 0.f;
        sb[416 + tid] = (tid < 200) ? b3[tid] : 0.f;
    }
    if (tid < 16) sb[624 + tid] = (tid < 10) ? b4[tid] : 0.f;

    float C[2][7][4];

    // --------------------- helpers ---------------------
    auto stage_w = [&](const uint4* src, int count, int buf) {
        uint4* d = ws + buf * 832;
        for (int i = tid; i < count; i += CTA_THREADS) cp16(d + i, src + i);
    };
    auto stage_x = [&](int ks, int buf) {
        float* d = xs + buf * 1280;
        int row = tid >> 2, seg = tid & 3;
        cp16(d + row * 20 + seg * 4, x + (size_t)(r0 + row) * 784 + ks * 16 + seg * 4);
    };
    auto zeroC = [&]() {
        #pragma unroll
        for (int mt = 0; mt < 2; ++mt)
            #pragma unroll
            for (int j = 0; j < 7; ++j)
                #pragma unroll
                for (int q = 0; q < 4; ++q) C[mt][j][q] = 0.f;
    };
    // h producer: plane-major fragment layout, conflict-free STS.32
    auto store_h = [&](const float* bias) {
        #pragma unroll
        for (int mt = 0; mt < 2; ++mt) {
            int mtile = mh * 2 + mt;
            for (int j = 0; j < cnt; ++j) {
                int J = js + j;
                float2 bb = *(const float2*)(bias + 8 * J + 2 * t);
                float v0 = fmaxf(C[mt][j][0] + bb.x, 0.f);
                float v1 = fmaxf(C[mt][j][1] + bb.y, 0.f);
                float v2 = fmaxf(C[mt][j][2] + bb.x, 0.f);
                float v3 = fmaxf(C[mt][j][3] + bb.y, 0.f);
                uint32_t H0, L0, H1, L1;
                split_pack(v0, v1, H0, L0);
                split_pack(v2, v3, H1, L1);
                int ks = J >> 1, kb = J & 1;
                int idx = (((ks * 4 + mtile) * 4) + 2 * kb) * 32 + lane;
                hfh[idx]      = H0;  hfl[idx]      = L0;   // reg p=0
                hfh[idx + 32] = H1;  hfl[idx + 32] = L1;   // reg p=1
            }
        }
    };
    // consumer: direct A-fragment loads, conflict-free LDS.32
    auto load_a_h = [&](int ks, uint32_t ah[2][4], uint32_t al[2][4]) {
        #pragma unroll
        for (int mt = 0; mt < 2; ++mt) {
            int base = ((ks * 4 + (mh * 2 + mt)) * 4) * 32 + lane;
            #pragma unroll
            for (int r = 0; r < 4; ++r) {
                ah[mt][r] = hfh[base + 32 * r];
                al[mt][r] = hfl[base + 32 * r];
            }
        }
    };
    auto mma_train = [&](const uint4* wb, const uint32_t ah[2][4], const uint32_t al[2][4]) {
        #pragma unroll
        for (int j = 0; j < 6; ++j) {
            uint4 w = wb[j * 32];
            #pragma unroll
            for (int mt = 0; mt < 2; ++mt) {
                mma_bf16(C[mt][j], ah[mt], w.x, w.y);   // hi*hi
                mma_bf16(C[mt][j], al[mt], w.x, w.y);   // lo*hi
                mma_bf16(C[mt][j], ah[mt], w.z, w.w);   // hi*lo
            }
        }
        if (cnt == 7) {
            uint4 w = wb[6 * 32];
            #pragma unroll
            for (int mt = 0; mt < 2; ++mt) {
                mma_bf16(C[mt][6], ah[mt], w.x, w.y);
                mma_bf16(C[mt][6], al[mt], w.x, w.y);
                mma_bf16(C[mt][6], ah[mt], w.z, w.w);
            }
        }
    };

    // =========================== Layer 1 (K=784) ===========================
    zeroC();
    stage_x(0, 0); stage_w(g_Wb1, 832, 0); CP_COMMIT;
    stage_x(1, 1); stage_w(g_Wb1 + 832, 832, 1); CP_COMMIT;
    {
        int cur = 0, st = 2;
        for (int ks = 0; ks < NK1; ++ks) {
            CP_WAIT1;
            __syncthreads();
            if (ks + 2 < NK1) { stage_x(ks + 2, st); stage_w(g_Wb1 + (ks + 2) * 832, 832, st); }
            CP_COMMIT;

            uint32_t ah[2][4], al[2][4];
            #pragma unroll
            for (int mt = 0; mt < 2; ++mt) {
                const float* xb = xs + cur * 1280 + (mh * 32 + mt * 16 + g) * 20;
                float2 p0 = *(const float2*)(xb + 2 * t);
                float2 p1 = *(const float2*)(xb + 160 + 2 * t);        // row+8
                float2 p2 = *(const float2*)(xb + 2 * t + 8);          // k+8
                float2 p3 = *(const float2*)(xb + 160 + 2 * t + 8);
                split_pack(p0.x, p0.y, ah[mt][0], al[mt][0]);
                split_pack(p1.x, p1.y, ah[mt][1], al[mt][1]);
                split_pack(p2.x, p2.y, ah[mt][2], al[mt][2]);
                split_pack(p3.x, p3.y, ah[mt][3], al[mt][3]);
            }
            mma_train(ws + cur * 832 + js * 32 + lane, ah, al);
            if (++cur == 3) cur = 0;
            if (++st  == 3) st  = 0;
        }
    }
    __syncthreads();
    store_h(sb);
    __syncthreads();

    // ======================= Layers 2 & 3 (K=208) ==========================
    const uint4* Wmid[2] = { g_Wb2, g_Wb3 };
    for (int l = 0; l < 2; ++l) {
        zeroC();
        stage_w(Wmid[l], 832, 0); CP_COMMIT;
        stage_w(Wmid[l] + 832, 832, 1); CP_COMMIT;
        int cur = 0, st = 2;
        for (int ks = 0; ks < NKH; ++ks) {
            CP_WAIT1;
            __syncthreads();
            if (ks + 2 < NKH) stage_w(Wmid[l] + (ks + 2) * 832, 832, st);
            CP_COMMIT;

            uint32_t ah[2][4], al[2][4];
            load_a_h(ks, ah, al);
            mma_train(ws + cur * 832 + js * 32 + lane, ah, al);
            if (++cur == 3) cur = 0;
            if (++st  == 3) st  = 0;
        }
        __syncthreads();
        store_h(sb + 208 * (l + 1));
        __syncthreads();
    }

    // =========================== Layer 4 (N=10) ============================
    float C4[2][4];
    #pragma unroll
    for (int mt = 0; mt < 2; ++mt)
        #pragma unroll
        for (int q = 0; q < 4; ++q) C4[mt][q] = 0.f;

    stage_w(g_Wb4, 64, 0); CP_COMMIT;
    stage_w(g_Wb4 + 64, 64, 1); CP_COMMIT;
    {
        int cur = 0, st = 2;
        for (int ks = 0; ks < NKH; ++ks) {
            CP_WAIT1;
            __syncthreads();
            if (ks + 2 < NKH) stage_w(g_Wb4 + (ks + 2) * 64, 64, st);
            CP_COMMIT;

            if (nq < 2) {
                uint32_t ah[2][4], al[2][4];
                load_a_h(ks, ah, al);
                uint4 w = ws[cur * 832 + nq * 32 + lane];
                #pragma unroll
                for (int mt = 0; mt < 2; ++mt) {
                    mma_bf16(C4[mt], ah[mt], w.x, w.y);
                    mma_bf16(C4[mt], al[mt], w.x, w.y);
                    mma_bf16(C4[mt], ah[mt], w.z, w.w);
                }
            }
            if (++cur == 3) cur = 0;
            if (++st  == 3) st  = 0;
        }
    }

    // output: cols 0..9 (warp nq covers cols 8nq+2t..+1; guard col<10)
    if (nq == 0 || (nq == 1 && t == 0)) {
        int col = 8 * nq + 2 * t;
        float2 bb = *(const float2*)(sb + 624 + col);
        #pragma unroll
        for (int mt = 0; mt < 2; ++mt) {
            int rowg = r0 + mh * 32 + mt * 16 + g;
            float2 o0 = { C4[mt][0] + bb.x, C4[mt][1] + bb.y };
            float2 o1 = { C4[mt][2] + bb.x, C4[mt][3] + bb.y };
            *(float2*)(out + (size_t)rowg * 10 + col)       = o0;
            *(float2*)(out + (size_t)(rowg + 8) * 10 + col) = o1;
        }
    }
}

// ---------------------------------------------------------------------------
extern "C" void kernel_launch(void* const* d_in, const int* in_sizes, int n_in,
                              void* d_out, int out_size) {
    const float* x  = (const float*)d_in[0];
    const float* cw = (const float*)d_in[1];
    const float* W1 = (const float*)d_in[2];
    const float* b1 = (const float*)d_in[3];
    const float* W2 = (const float*)d_in[4];
    const float* b2 = (const float*)d_in[5];
    const float* W3 = (const float*)d_in[6];
    const float* b3 = (const float*)d_in[7];
    const float* W4 = (const float*)d_in[8];
    const float* b4 = (const float*)d_in[9];
    float* out = (float*)d_out;

    cudaFuncSetAttribute(mlp_kernel, cudaFuncAttributeMaxDynamicSharedMemorySize, SMEM_BYTES);

    prep_kernel<<<247, CTA_THREADS>>>(cw, W1, W2, W3, W4);
    mlp_kernel<<<1024, CTA_THREADS, SMEM_BYTES>>>(x, b1, b2, b3, b4, out);
}